// round 1
// baseline (speedup 1.0000x reference)
#include <cuda_runtime.h>
#include <math_constants.h>

#define Bb 16
#define Ss 2048
#define Hh 1024
#define Mm (Bb * Ss)   // 32768

// scratch: q[b,o] = Wh @ h_b + bias
__device__ float g_q[Bb * Hh];

// ---------------------------------------------------------------------------
// Kernel 1: q[b,o] = dot(h[b,:], attn_W[o, 0:H]) + attn_b[o]
// grid (B, H/8), block 256 (8 warps, one o per warp)
// ---------------------------------------------------------------------------
__global__ void q_kernel(const float* __restrict__ h,
                         const float* __restrict__ W,
                         const float* __restrict__ bias) {
    int b = blockIdx.x;
    __shared__ float hs[Hh];
    for (int i = threadIdx.x; i < Hh; i += blockDim.x) hs[i] = h[b * Hh + i];
    __syncthreads();

    int warp = threadIdx.x >> 5;
    int lane = threadIdx.x & 31;
    int o = blockIdx.y * 8 + warp;

    const float* Wrow = W + (size_t)o * (2 * Hh);  // Wh row
    float acc = 0.f;
    #pragma unroll 8
    for (int k = lane; k < Hh; k += 32) acc += hs[k] * Wrow[k];
    #pragma unroll
    for (int off = 16; off; off >>= 1) acc += __shfl_xor_sync(0xffffffffu, acc, off);
    if (lane == 0) g_q[b * Hh + o] = acc + bias[o];
}

// ---------------------------------------------------------------------------
// Kernel 2: fused scores GEMM
//   scores[m] = sum_n v[n] * relu( sum_k A[m,k]*Wa[n,k] + q[b,n] )
// A = encoder_outputs (M x H), Wa[n,k] = attn_W[n*2H + H + k]
// BM=64, BN=64, BK=32, 256 threads, 4x4 microtile. N-loop outside K-loop,
// epilogue folds relu + v-dot so energy is never stored.
// ---------------------------------------------------------------------------
#define BM 64
#define BN 64
#define BK 32

__global__ void __launch_bounds__(256, 4)
scores_kernel(const float* __restrict__ A,
              const float* __restrict__ W,
              const float* __restrict__ v,
              float* __restrict__ out_scores) {
    __shared__ float As[BK][BM];
    __shared__ float Bs[BK][BN];
    __shared__ float sred[BM][17];

    const int block_m = blockIdx.x * BM;
    const int b = block_m / Ss;            // BM divides S, so one batch per block
    const int tid = threadIdx.x;
    const int tx = tid & 15;
    const int ty = tid >> 4;

    const float* qb = g_q + b * Hh;
    float part[4] = {0.f, 0.f, 0.f, 0.f};

    for (int n0 = 0; n0 < Hh; n0 += BN) {
        float acc[4][4] = {};

        for (int k0 = 0; k0 < Hh; k0 += BK) {
            // cooperative loads: 64 rows x 32 cols each for A and Wa
            #pragma unroll
            for (int r = 0; r < 2; r++) {
                int f   = tid + r * 256;   // 0..511
                int row = f >> 3;          // 0..63
                int q4  = f & 7;           // float4 index along k
                float4 av = *(const float4*)(A + (size_t)(block_m + row) * Hh + k0 + q4 * 4);
                As[q4 * 4 + 0][row] = av.x;
                As[q4 * 4 + 1][row] = av.y;
                As[q4 * 4 + 2][row] = av.z;
                As[q4 * 4 + 3][row] = av.w;
                float4 wv = *(const float4*)(W + (size_t)(n0 + row) * (2 * Hh) + Hh + k0 + q4 * 4);
                Bs[q4 * 4 + 0][row] = wv.x;
                Bs[q4 * 4 + 1][row] = wv.y;
                Bs[q4 * 4 + 2][row] = wv.z;
                Bs[q4 * 4 + 3][row] = wv.w;
            }
            __syncthreads();

            #pragma unroll
            for (int k = 0; k < BK; k++) {
                float4 a4 = *(const float4*)&As[k][ty * 4];
                float4 b4 = *(const float4*)&Bs[k][tx * 4];
                acc[0][0] += a4.x * b4.x; acc[0][1] += a4.x * b4.y;
                acc[0][2] += a4.x * b4.z; acc[0][3] += a4.x * b4.w;
                acc[1][0] += a4.y * b4.x; acc[1][1] += a4.y * b4.y;
                acc[1][2] += a4.y * b4.z; acc[1][3] += a4.y * b4.w;
                acc[2][0] += a4.z * b4.x; acc[2][1] += a4.z * b4.y;
                acc[2][2] += a4.z * b4.z; acc[2][3] += a4.z * b4.w;
                acc[3][0] += a4.w * b4.x; acc[3][1] += a4.w * b4.y;
                acc[3][2] += a4.w * b4.z; acc[3][3] += a4.w * b4.w;
            }
            __syncthreads();
        }

        // epilogue: relu(+q) * v, reduce over this n-chunk
        #pragma unroll
        for (int j = 0; j < 4; j++) {
            int n = n0 + tx * 4 + j;
            float qn = __ldg(&qb[n]);
            float vn = __ldg(&v[n]);
            #pragma unroll
            for (int i = 0; i < 4; i++) {
                float e = fmaxf(acc[i][j] + qn, 0.f);
                part[i] += e * vn;
            }
        }
    }

    // cross-thread reduce: 16 tx-partials per row
    #pragma unroll
    for (int i = 0; i < 4; i++) sred[ty * 4 + i][tx] = part[i];
    __syncthreads();
    if (tid < BM) {
        float s = 0.f;
        #pragma unroll
        for (int x = 0; x < 16; x++) s += sred[tid][x];
        out_scores[block_m + tid] = s;
    }
}

// ---------------------------------------------------------------------------
// Kernel 3: in-place softmax over S per batch. grid = B, block = 256
// ---------------------------------------------------------------------------
__global__ void softmax_kernel(float* __restrict__ w) {
    int b = blockIdx.x;
    float* row = w + (size_t)b * Ss;
    __shared__ float red[256];
    int tid = threadIdx.x;

    float m = -CUDART_INF_F;
    for (int i = tid; i < Ss; i += 256) m = fmaxf(m, row[i]);
    red[tid] = m;
    __syncthreads();
    for (int s = 128; s; s >>= 1) {
        if (tid < s) red[tid] = fmaxf(red[tid], red[tid + s]);
        __syncthreads();
    }
    m = red[0];
    __syncthreads();

    float sum = 0.f;
    for (int i = tid; i < Ss; i += 256) {
        float e = __expf(row[i] - m);
        row[i] = e;
        sum += e;
    }
    red[tid] = sum;
    __syncthreads();
    for (int s = 128; s; s >>= 1) {
        if (tid < s) red[tid] += red[tid + s];
        __syncthreads();
    }
    float inv = 1.f / red[0];
    __syncthreads();
    for (int i = tid; i < Ss; i += 256) row[i] *= inv;
}

// ---------------------------------------------------------------------------
// Kernel 4: context[b,h] = sum_s w[b,s] * A[b,s,h]. grid (H/256, B), block 256
// ---------------------------------------------------------------------------
__global__ void context_kernel(const float* __restrict__ A,
                               const float* __restrict__ w,
                               float* __restrict__ ctx) {
    int b = blockIdx.y;
    int hcol = blockIdx.x * 256 + threadIdx.x;
    __shared__ float ws[Ss];
    for (int i = threadIdx.x; i < Ss; i += 256) ws[i] = w[(size_t)b * Ss + i];
    __syncthreads();

    const float* Ab = A + (size_t)b * Ss * Hh + hcol;
    float acc = 0.f;
    #pragma unroll 4
    for (int s = 0; s < Ss; s++) acc += ws[s] * Ab[(size_t)s * Hh];
    ctx[b * Hh + hcol] = acc;
}

// ---------------------------------------------------------------------------
extern "C" void kernel_launch(void* const* d_in, const int* in_sizes, int n_in,
                              void* d_out, int out_size) {
    const float* h    = (const float*)d_in[0];
    // d_in[1] = c (unused)
    const float* a    = (const float*)d_in[2];
    const float* W    = (const float*)d_in[3];
    const float* bias = (const float*)d_in[4];
    const float* vW   = (const float*)d_in[5];

    float* ctx_out  = (float*)d_out;              // (B,1,H)
    float* attn_out = (float*)d_out + Bb * Hh;    // (B,S)

    q_kernel<<<dim3(Bb, Hh / 8), 256>>>(h, W, bias);
    scores_kernel<<<Mm / BM, 256>>>(a, W, vW, attn_out);
    softmax_kernel<<<Bb, 256>>>(attn_out);
    context_kernel<<<dim3(Hh / 256, Bb), 256>>>(a, attn_out, ctx_out);
}

// round 3
// speedup vs baseline: 5.5197x; 5.5197x over previous
#include <cuda_runtime.h>
#include <math_constants.h>
#include <cstdint>

#define Bb 16
#define Ss 2048
#define Hh 1024
#define Mm (Bb * Ss)   // 32768

__device__ float g_q[Bb * Hh];
__device__ float g_ctx_part[16 * 16 * 1024];

// ---------------------------------------------------------------- helpers
__device__ __forceinline__ uint32_t smem_u32(const void* p) {
    uint32_t a;
    asm("{ .reg .u64 t; cvta.to.shared.u64 t, %1; cvt.u32.u64 %0, t; }" : "=r"(a) : "l"(p));
    return a;
}
__device__ __forceinline__ uint32_t f2tf(float f) {
    uint32_t u; asm("cvt.rna.tf32.f32 %0, %1;" : "=r"(u) : "f"(f)); return u;
}
__device__ __forceinline__ void cp_async16(uint32_t dst, const void* src) {
    asm volatile("cp.async.cg.shared.global [%0], [%1], 16;" :: "r"(dst), "l"(src));
}
__device__ __forceinline__ void cp_commit() { asm volatile("cp.async.commit_group;"); }
__device__ __forceinline__ void cp_wait1()  { asm volatile("cp.async.wait_group 1;"); }
__device__ __forceinline__ void cp_wait0()  { asm volatile("cp.async.wait_group 0;"); }

__device__ __forceinline__ void mma_tf32(float* d, const uint32_t* a, const uint32_t* b) {
    asm volatile(
        "mma.sync.aligned.m16n8k8.row.col.f32.tf32.tf32.f32 "
        "{%0,%1,%2,%3}, {%4,%5,%6,%7}, {%8,%9}, {%0,%1,%2,%3};"
        : "+f"(d[0]), "+f"(d[1]), "+f"(d[2]), "+f"(d[3])
        : "r"(a[0]), "r"(a[1]), "r"(a[2]), "r"(a[3]), "r"(b[0]), "r"(b[1]));
}

// ---------------------------------------------------------------------------
// Kernel 0: zero the scores region (d_out is poisoned)
// ---------------------------------------------------------------------------
__global__ void zero_scores(float* __restrict__ s) {
    s[blockIdx.x * 1024 + threadIdx.x] = 0.f;
}

// ---------------------------------------------------------------------------
// Kernel 1: q[b,o] = dot(h[b,:], attn_W[o, 0:H]) + attn_b[o]
// ---------------------------------------------------------------------------
__global__ void q_kernel(const float* __restrict__ h,
                         const float* __restrict__ W,
                         const float* __restrict__ bias) {
    int b = blockIdx.x;
    __shared__ float hs[Hh];
    for (int i = threadIdx.x; i < Hh; i += blockDim.x) hs[i] = h[b * Hh + i];
    __syncthreads();
    int warp = threadIdx.x >> 5, lane = threadIdx.x & 31;
    int o = blockIdx.y * 8 + warp;
    const float* Wrow = W + (size_t)o * (2 * Hh);
    float acc = 0.f;
    #pragma unroll 8
    for (int k = lane; k < Hh; k += 32) acc += hs[k] * Wrow[k];
    #pragma unroll
    for (int off = 16; off; off >>= 1) acc += __shfl_xor_sync(0xffffffffu, acc, off);
    if (lane == 0) g_q[b * Hh + o] = acc + bias[o];
}

// ---------------------------------------------------------------------------
// Kernel 2: fused scores GEMM via tf32 mma.sync (m16n8k8).
// Grid (M/128, N/128). CTA tile 128x128, BK=16, cp.async double buffer.
// Smem tiles row-major padded to 20 floats/row (conflict-free fragment LDS).
// Epilogue: relu(+q)*v row-reduction in registers, atomicAdd row partials.
// ---------------------------------------------------------------------------
#define BKI 16
#define PAD 20
#define NIT (Hh / BKI)   // 64

__global__ void __launch_bounds__(256)
scores_mma(const float* __restrict__ A,
           const float* __restrict__ W,
           const float* __restrict__ v,
           float* __restrict__ out_scores) {
    __shared__ float As[2][128][PAD];
    __shared__ float Bs[2][128][PAD];
    __shared__ float s_q[128];
    __shared__ float s_v[128];

    const int tid  = threadIdx.x;
    const int wid  = tid >> 5, lane = tid & 31;
    const int g    = lane >> 2, t = lane & 3;
    const int bm   = blockIdx.x;          // m block (128 rows)
    const int bn   = blockIdx.y;          // n block (128 cols)
    const int b    = (bm * 128) >> 11;    // batch
    const int wm   = (wid & 3) * 32;      // warp m offset
    const int wn   = (wid >> 2) * 64;     // warp n offset

    if (tid < 128) {
        s_q[tid] = g_q[b * Hh + bn * 128 + tid];
        s_v[tid] = v[bn * 128 + tid];
    }

    const float* Agbase = A + (size_t)(bm * 128) * Hh;
    const float* Wgbase = W + (size_t)(bn * 128) * (2 * Hh) + Hh;

    // per-thread cp.async assignments: 512 float4 per tile, 2 per thread
    const int r0 = tid >> 2, c0 = (tid & 3);          // rows 0..63
    const int r1 = r0 + 64;

    uint32_t sA[2][2], sB[2][2];
    #pragma unroll
    for (int s = 0; s < 2; s++) {
        sA[s][0] = smem_u32(&As[s][r0][c0 * 4]);
        sA[s][1] = smem_u32(&As[s][r1][c0 * 4]);
        sB[s][0] = smem_u32(&Bs[s][r0][c0 * 4]);
        sB[s][1] = smem_u32(&Bs[s][r1][c0 * 4]);
    }

    auto load_stage = [&](int s, int k0) {
        cp_async16(sA[s][0], Agbase + (size_t)r0 * Hh + k0 + c0 * 4);
        cp_async16(sA[s][1], Agbase + (size_t)r1 * Hh + k0 + c0 * 4);
        cp_async16(sB[s][0], Wgbase + (size_t)r0 * (2 * Hh) + k0 + c0 * 4);
        cp_async16(sB[s][1], Wgbase + (size_t)r1 * (2 * Hh) + k0 + c0 * 4);
        cp_commit();
    };

    float acc[2][8][4] = {};

    load_stage(0, 0);

    for (int it = 0; it < NIT; it++) {
        const int buf = it & 1;
        if (it + 1 < NIT) { load_stage(buf ^ 1, (it + 1) * BKI); cp_wait1(); }
        else              { cp_wait0(); }
        __syncthreads();

        #pragma unroll
        for (int ks = 0; ks < 2; ks++) {
            const int kb = ks * 8;
            uint32_t af[2][4];
            #pragma unroll
            for (int i = 0; i < 2; i++) {
                const int mr = wm + i * 16;
                af[i][0] = f2tf(As[buf][mr + g    ][kb + t    ]);
                af[i][1] = f2tf(As[buf][mr + g + 8][kb + t    ]);
                af[i][2] = f2tf(As[buf][mr + g    ][kb + t + 4]);
                af[i][3] = f2tf(As[buf][mr + g + 8][kb + t + 4]);
            }
            #pragma unroll
            for (int j = 0; j < 8; j++) {
                uint32_t bf[2];
                bf[0] = f2tf(Bs[buf][wn + j * 8 + g][kb + t    ]);
                bf[1] = f2tf(Bs[buf][wn + j * 8 + g][kb + t + 4]);
                mma_tf32(acc[0][j], af[0], bf);
                mma_tf32(acc[1][j], af[1], bf);
            }
        }
        __syncthreads();
    }

    // epilogue: relu(+q)*v, reduce cols
    float rs[2][2] = {};
    #pragma unroll
    for (int j = 0; j < 8; j++) {
        const int nl = wn + j * 8 + 2 * t;
        const float q0 = s_q[nl], q1 = s_q[nl + 1];
        const float v0 = s_v[nl], v1 = s_v[nl + 1];
        #pragma unroll
        for (int i = 0; i < 2; i++) {
            rs[i][0] += fmaxf(acc[i][j][0] + q0, 0.f) * v0 + fmaxf(acc[i][j][1] + q1, 0.f) * v1;
            rs[i][1] += fmaxf(acc[i][j][2] + q0, 0.f) * v0 + fmaxf(acc[i][j][3] + q1, 0.f) * v1;
        }
    }
    // quad reduce over t
    #pragma unroll
    for (int off = 1; off < 4; off <<= 1) {
        #pragma unroll
        for (int i = 0; i < 2; i++) {
            rs[i][0] += __shfl_xor_sync(0xffffffffu, rs[i][0], off);
            rs[i][1] += __shfl_xor_sync(0xffffffffu, rs[i][1], off);
        }
    }
    if (t == 0) {
        const int rowb = bm * 128 + wm;
        #pragma unroll
        for (int i = 0; i < 2; i++) {
            atomicAdd(&out_scores[rowb + i * 16 + g    ], rs[i][0]);
            atomicAdd(&out_scores[rowb + i * 16 + g + 8], rs[i][1]);
        }
    }
}

// ---------------------------------------------------------------------------
// Kernel 3: in-place softmax over S per batch
// ---------------------------------------------------------------------------
__global__ void softmax_kernel(float* __restrict__ w) {
    int b = blockIdx.x;
    float* row = w + (size_t)b * Ss;
    __shared__ float red[256];
    int tid = threadIdx.x;

    float m = -CUDART_INF_F;
    for (int i = tid; i < Ss; i += 256) m = fmaxf(m, row[i]);
    red[tid] = m; __syncthreads();
    for (int s = 128; s; s >>= 1) { if (tid < s) red[tid] = fmaxf(red[tid], red[tid + s]); __syncthreads(); }
    m = red[0]; __syncthreads();

    float sum = 0.f;
    for (int i = tid; i < Ss; i += 256) { float e = __expf(row[i] - m); row[i] = e; sum += e; }
    red[tid] = sum; __syncthreads();
    for (int s = 128; s; s >>= 1) { if (tid < s) red[tid] += red[tid + s]; __syncthreads(); }
    float inv = 1.f / red[0]; __syncthreads();
    for (int i = tid; i < Ss; i += 256) row[i] *= inv;
}

// ---------------------------------------------------------------------------
// Kernel 4a: context partials. grid (16 schunks, B), block 256
// ---------------------------------------------------------------------------
__global__ void context_part_kernel(const float* __restrict__ A,
                                    const float* __restrict__ w) {
    int sc = blockIdx.x, b = blockIdx.y;
    __shared__ float ws[128];
    int tid = threadIdx.x;
    if (tid < 128) ws[tid] = w[(size_t)b * Ss + sc * 128 + tid];
    __syncthreads();
    int h4 = tid * 4;
    const float* Ab = A + ((size_t)b * Ss + sc * 128) * Hh + h4;
    float4 acc = {0.f, 0.f, 0.f, 0.f};
    #pragma unroll 4
    for (int s = 0; s < 128; s++) {
        float4 av = __ldg((const float4*)(Ab + (size_t)s * Hh));
        float wv = ws[s];
        acc.x += wv * av.x; acc.y += wv * av.y; acc.z += wv * av.z; acc.w += wv * av.w;
    }
    *(float4*)(g_ctx_part + ((size_t)(b * 16 + sc) * Hh) + h4) = acc;
}

// Kernel 4b: reduce partials
__global__ void context_reduce_kernel(float* __restrict__ ctx) {
    int b = blockIdx.x;
    int h4 = threadIdx.x * 4;
    float4 s = {0.f, 0.f, 0.f, 0.f};
    #pragma unroll
    for (int j = 0; j < 16; j++) {
        float4 p = *(const float4*)(g_ctx_part + ((size_t)(b * 16 + j) * Hh) + h4);
        s.x += p.x; s.y += p.y; s.z += p.z; s.w += p.w;
    }
    *(float4*)(ctx + (size_t)b * Hh + h4) = s;
}

// ---------------------------------------------------------------------------
extern "C" void kernel_launch(void* const* d_in, const int* in_sizes, int n_in,
                              void* d_out, int out_size) {
    const float* h    = (const float*)d_in[0];
    // d_in[1] = c (unused)
    const float* a    = (const float*)d_in[2];
    const float* W    = (const float*)d_in[3];
    const float* bias = (const float*)d_in[4];
    const float* vW   = (const float*)d_in[5];

    float* ctx_out  = (float*)d_out;              // (B,1,H)
    float* attn_out = (float*)d_out + Bb * Hh;    // (B,S)

    zero_scores<<<Mm / 1024, 1024>>>(attn_out);
    q_kernel<<<dim3(Bb, Hh / 8), 256>>>(h, W, bias);
    scores_mma<<<dim3(Mm / 128, Hh / 128), 256>>>(a, W, vW, attn_out);
    softmax_kernel<<<Bb, 256>>>(attn_out);
    context_part_kernel<<<dim3(16, Bb), 256>>>(a, attn_out);
    context_reduce_kernel<<<Bb, 256>>>(ctx_out);
}